// round 3
// baseline (speedup 1.0000x reference)
#include <cuda_runtime.h>

#define NB 2
#define NS 2048
#define ND 4096
#define NH 16
#define NHD 256

#define BM 128
#define BN 128
#define BK 16
#define ASTR 20
#define BSTR 136

// Scratch (allocation-free rule: __device__ globals)
static __device__ float g_qkv[(size_t)NB*NS*3*ND];      // [B,S,3D]
static __device__ float g_q[(size_t)NB*NH*NS*NHD];      // [B,H,S,hd]
static __device__ float g_k[(size_t)NB*NH*NS*NHD];      // [B,H,S,hd]
static __device__ float g_v[(size_t)NB*NH*NS*NHD];      // [B,H,S,hd]
static __device__ float g_sc[(size_t)NB*NH*NS*NS];      // [B,H,S,S] scores/probs
static __device__ float g_at[(size_t)NB*NS*ND];         // [B,S,D] attn out

__device__ __forceinline__ unsigned f2tf(float f){
  unsigned u; asm("cvt.rna.tf32.f32 %0,%1;":"=r"(u):"f"(f)); return u;
}

__device__ __forceinline__ void mmaop(float* c, const unsigned* a, const unsigned* b){
  asm volatile(
    "mma.sync.aligned.m16n8k8.row.col.f32.tf32.tf32.f32 "
    "{%0,%1,%2,%3},{%4,%5,%6,%7},{%8,%9},{%0,%1,%2,%3};\n"
    : "+f"(c[0]),"+f"(c[1]),"+f"(c[2]),"+f"(c[3])
    : "r"(a[0]),"r"(a[1]),"r"(a[2]),"r"(a[3]),"r"(b[0]),"r"(b[1]));
}

// Generic batched tf32 GEMM: C[z] = A[z] * op(B[z])
// transB: B source is row-major [N,K] (we compute A * B^T)
// causal==1: skip block-cols above diagonal (scores GEMM, M==N)
// causal==2: limit K loop to (bm+1)*BM (PV GEMM; P is zero beyond that)
// C batch offset = (z/cdiv)*cs1 + (z%cdiv)*cs2
__global__ __launch_bounds__(256) void gemm_tf32(
  const float* __restrict__ A, const float* __restrict__ B, float* __restrict__ C,
  int M,int N,int K,int lda,int ldb,int ldc,
  long long sA,long long sB,long long cs1,long long cs2,int cdiv,
  int transB,int causal)
{
  const int bn=blockIdx.x, bm=blockIdx.y, z=blockIdx.z;
  if (causal==1 && bn>bm) return;
  int kend=K;
  if (causal==2){ int ke=(bm+1)*BM; if(ke<kend) kend=ke; }

  const float* Ab = A + (long long)z*sA;
  const float* Bb = B + (long long)z*sB;
  const long long coff = (long long)(z/cdiv)*cs1 + (long long)(z%cdiv)*cs2;

  __shared__ unsigned As[BM*ASTR];   // [128][16] pad->20 (conflict-free frags)
  __shared__ unsigned Bs[BK*BSTR];   // [16][128] pad->136 (conflict-free frags)

  const int tid=threadIdx.x;
  const int warp=tid>>5, lane=tid&31;
  const int wm=warp>>2, wn=warp&3;       // 2x4 warp grid, warp tile 64x32
  const int gq=lane>>2, tg=lane&3;

  float acc[4][4][4];
#pragma unroll
  for(int i=0;i<4;i++)
#pragma unroll
    for(int j=0;j<4;j++)
#pragma unroll
      for(int l=0;l<4;l++) acc[i][j][l]=0.f;

  const int arow=tid>>2, ac4=tid&3;
  const float* Ap = Ab + (long long)(bm*BM+arow)*lda + ac4*4;
  const float* Bp;
  int bkk=0,bn4=0,btn=0,btc4=0;
  if(!transB){
    bkk=tid>>5; bn4=tid&31;
    Bp = Bb + (long long)bkk*ldb + bn*BN + bn4*4;
  }else{
    btn=tid>>2; btc4=tid&3;
    Bp = Bb + (long long)(bn*BN+btn)*ldb + btc4*4;
  }

  float4 ar0,ar1,br0,br1;
  ar0 = *(const float4*)(Ap);
  ar1 = *(const float4*)(Ap + 64LL*lda);
  if(!transB){ br0=*(const float4*)(Bp); br1=*(const float4*)(Bp+8LL*ldb); }
  else       { br0=*(const float4*)(Bp); br1=*(const float4*)(Bp+64LL*ldb); }

  const int nk = kend/BK;
  for(int kt=0; kt<nk; ++kt){
    __syncthreads();
    { // stage A (convert to tf32 bits)
      uint4 u; u.x=f2tf(ar0.x);u.y=f2tf(ar0.y);u.z=f2tf(ar0.z);u.w=f2tf(ar0.w);
      *(uint4*)&As[arow*ASTR+ac4*4]=u;
      u.x=f2tf(ar1.x);u.y=f2tf(ar1.y);u.z=f2tf(ar1.z);u.w=f2tf(ar1.w);
      *(uint4*)&As[(arow+64)*ASTR+ac4*4]=u;
    }
    if(!transB){
      uint4 u; u.x=f2tf(br0.x);u.y=f2tf(br0.y);u.z=f2tf(br0.z);u.w=f2tf(br0.w);
      *(uint4*)&Bs[bkk*BSTR+bn4*4]=u;
      u.x=f2tf(br1.x);u.y=f2tf(br1.y);u.z=f2tf(br1.z);u.w=f2tf(br1.w);
      *(uint4*)&Bs[(bkk+8)*BSTR+bn4*4]=u;
    }else{
      Bs[(btc4*4+0)*BSTR+btn]=f2tf(br0.x);
      Bs[(btc4*4+1)*BSTR+btn]=f2tf(br0.y);
      Bs[(btc4*4+2)*BSTR+btn]=f2tf(br0.z);
      Bs[(btc4*4+3)*BSTR+btn]=f2tf(br0.w);
      Bs[(btc4*4+0)*BSTR+btn+64]=f2tf(br1.x);
      Bs[(btc4*4+1)*BSTR+btn+64]=f2tf(br1.y);
      Bs[(btc4*4+2)*BSTR+btn+64]=f2tf(br1.z);
      Bs[(btc4*4+3)*BSTR+btn+64]=f2tf(br1.w);
    }
    __syncthreads();

    if(kt+1<nk){ // prefetch next tile into registers (overlaps with compute)
      int k0=(kt+1)*BK;
      ar0=*(const float4*)(Ap+k0);
      ar1=*(const float4*)(Ap+64LL*lda+k0);
      if(!transB){
        const float* p = Bp + (long long)k0*ldb;
        br0=*(const float4*)p; br1=*(const float4*)(p+8LL*ldb);
      }else{
        br0=*(const float4*)(Bp+k0);
        br1=*(const float4*)(Bp+64LL*ldb+k0);
      }
    }

#pragma unroll
    for(int ks=0;ks<2;ks++){
      const int kk=ks*8;
      unsigned a[4][4], b[4][2];
#pragma unroll
      for(int mi=0;mi<4;mi++){
        int rb=wm*64+mi*16+gq;
        a[mi][0]=As[rb*ASTR+kk+tg];
        a[mi][1]=As[(rb+8)*ASTR+kk+tg];
        a[mi][2]=As[rb*ASTR+kk+tg+4];
        a[mi][3]=As[(rb+8)*ASTR+kk+tg+4];
      }
#pragma unroll
      for(int ni=0;ni<4;ni++){
        int cb=wn*32+ni*8+gq;
        b[ni][0]=Bs[(kk+tg)*BSTR+cb];
        b[ni][1]=Bs[(kk+tg+4)*BSTR+cb];
      }
#pragma unroll
      for(int mi=0;mi<4;mi++)
#pragma unroll
        for(int ni=0;ni<4;ni++)
          mmaop(acc[mi][ni], a[mi], b[ni]);
    }
  }

#pragma unroll
  for(int mi=0;mi<4;mi++){
    int r0 = bm*BM + wm*64 + mi*16 + gq;
#pragma unroll
    for(int ni=0;ni<4;ni++){
      int c0 = bn*BN + wn*32 + ni*8 + tg*2;
      float* p = C + coff + (long long)r0*ldc + c0;
      *(float2*)p             = make_float2(acc[mi][ni][0], acc[mi][ni][1]);
      *(float2*)(p + 8LL*ldc) = make_float2(acc[mi][ni][2], acc[mi][ni][3]);
    }
  }
}

// Split qkv -> q,k,v in [B,H,S,hd] layout, applying GPT-J rope to q,k (first 64 dims)
__global__ __launch_bounds__(256) void prep_rope(
  const float* __restrict__ qkv, const int* __restrict__ pos_ids,
  float* __restrict__ q, float* __restrict__ k, float* __restrict__ v)
{
  int t = blockIdx.x*blockDim.x + threadIdx.x;   // t = (((tensor*B+b)*H+h)*S+s)*64 + d4
  int d4 = t & 63; int r = t>>6;
  int s = r & (NS-1); r >>= 11;
  int h = r & (NH-1); r >>= 4;
  int b = r & 1; int tensor = r>>1;

  float4 x = *(const float4*)(qkv + (long long)(b*NS+s)*(3*ND) + tensor*ND + h*NHD + d4*4);

  if (tensor<2 && d4<16){  // d = d4*4 < 64 : rotary region
    float pos = (float)pos_ids[b*NS+s];
    int i0 = d4*2, i1 = d4*2+1;  // pair indices; inv_freq_i = theta^(-2i/64)
    float inv0 = 1.0f/powf(10000.0f, (float)(2*i0)*(1.0f/64.0f));
    float inv1 = 1.0f/powf(10000.0f, (float)(2*i1)*(1.0f/64.0f));
    float f0 = pos*inv0, f1 = pos*inv1;
    float c0=cosf(f0), s0=sinf(f0), c1=cosf(f1), s1=sinf(f1);
    float nx = x.x*c0 - x.y*s0;
    float ny = x.y*c0 + x.x*s0;
    float nz = x.z*c1 - x.w*s1;
    float nw = x.w*c1 + x.z*s1;
    x = make_float4(nx,ny,nz,nw);
  }
  float* dst = (tensor==0)? q : (tensor==1)? k : v;
  *(float4*)(dst + (long long)((b*NH+h)*NS+s)*NHD + d4*4) = x;
}

// In-place causal softmax over scores rows; writes zeros for masked cols up to
// the next 128 boundary (so the PV GEMM's causal K-limit reads only valid data).
__global__ __launch_bounds__(256) void softmax_causal(float* __restrict__ sc){
  const int m=blockIdx.x, z=blockIdx.y;
  float* row = sc + ((long long)z*NS + m)*NS;
  const int valid=m+1;
  const int zlim=((m>>7)+1)<<7;
  const int tid=threadIdx.x;
  const float scale=0.0625f;   // hd^-0.5 = 1/16
  float vals[8];
  float mx=-3.0e38f;
#pragma unroll
  for(int i=0;i<8;i++){
    int j=tid+(i<<8);
    float vv=-3.0e38f;
    if(j<valid) vv=row[j]*scale;
    vals[i]=vv;
    mx=fmaxf(mx,vv);
  }
  __shared__ float redm[8], reds[8];
#pragma unroll
  for(int o=16;o>0;o>>=1) mx=fmaxf(mx,__shfl_xor_sync(0xffffffffu,mx,o));
  if((tid&31)==0) redm[tid>>5]=mx;
  __syncthreads();
  mx=redm[0];
#pragma unroll
  for(int i=1;i<8;i++) mx=fmaxf(mx,redm[i]);

  float sum=0.f;
#pragma unroll
  for(int i=0;i<8;i++){
    float e = expf(vals[i]-mx);   // masked: exp(-huge) -> 0
    vals[i]=e; sum+=e;
  }
#pragma unroll
  for(int o=16;o>0;o>>=1) sum+=__shfl_xor_sync(0xffffffffu,sum,o);
  if((tid&31)==0) reds[tid>>5]=sum;
  __syncthreads();
  sum=0.f;
#pragma unroll
  for(int i=0;i<8;i++) sum+=reds[i];
  float inv=1.0f/sum;
#pragma unroll
  for(int i=0;i<8;i++){
    int j=tid+(i<<8);
    if(j<zlim) row[j] = (j<valid)? vals[i]*inv : 0.f;
  }
}

extern "C" void kernel_launch(void* const* d_in, const int* in_sizes, int n_in,
                              void* d_out, int out_size)
{
  const int*   pos  = (const int*)d_in[0];
  const float* hid  = (const float*)d_in[1];
  const float* wqkv = (const float*)d_in[2];
  const float* wout = (const float*)d_in[3];
  float* out = (float*)d_out;

  float *qkv,*q,*k,*v,*sc,*at;
  cudaGetSymbolAddress((void**)&qkv,g_qkv);
  cudaGetSymbolAddress((void**)&q,  g_q);
  cudaGetSymbolAddress((void**)&k,  g_k);
  cudaGetSymbolAddress((void**)&v,  g_v);
  cudaGetSymbolAddress((void**)&sc, g_sc);
  cudaGetSymbolAddress((void**)&at, g_at);

  // 1) qkv = X @ Wqkv   [4096 x 12288 x 4096]
  gemm_tf32<<<dim3((3*ND)/BN,(NB*NS)/BM,1),256>>>(
      hid,wqkv,qkv, NB*NS,3*ND,ND, ND,3*ND,3*ND, 0,0, 0,0,1, 0,0);

  // 2) split + rope -> q,k,v in [B,H,S,hd]
  prep_rope<<<(3*NB*NH*NS*64)/256,256>>>(qkv,pos,q,k,v);

  // 3) scores[z] = Q @ K^T (batched z=b*H+h, causal block-skip)
  gemm_tf32<<<dim3(NS/BN,NS/BM,NB*NH),256>>>(
      q,k,sc, NS,NS,NHD, NHD,NHD,NS,
      (long long)NS*NHD,(long long)NS*NHD,
      (long long)NS*NS,0,1, 1,1);

  // 4) causal softmax in place
  softmax_causal<<<dim3(NS,NB*NH),256>>>(sc);

  // 5) attn[z] = P @ V, written directly to [B,S,D] (causal K-limit)
  gemm_tf32<<<dim3(NHD/BN,NS/BM,NB*NH),256>>>(
      sc,v,at, NS,NHD,NS, NS,NHD,ND,
      (long long)NS*NS,(long long)NS*NHD,
      (long long)NS*ND,(long long)NHD,NH, 0,2);

  // 6) out = attn @ Wout
  gemm_tf32<<<dim3(ND/BN,(NB*NS)/BM,1),256>>>(
      at,wout,out, NB*NS,ND,ND, ND,ND,ND, 0,0, 0,0,1, 0,0);
}